// round 17
// baseline (speedup 1.0000x reference)
#include <cuda_runtime.h>
#include <math.h>

#define N_IN        1024
#define N_OUT       4096
#define BATCH       8
#define OC          64
#define THREADS     1024
#define M_PER_BLOCK 256
#define NSUB        4                      // lanes cooperating per target (within warp)

#define GRID        13
#define NCELL       (GRID * GRID)          // 169
#define INV_CELL    (GRID / 4.0f)          // 3.25
// natural-log cutoff: terms with exponent < -T are dropped.
// T=45 -> e^-45 ~ 3e-20; with the reference's +1e-8 denominator guard this is
// ~1e-8 absolute error worst case. Far below the 1e-3 rel_err gate.
#define CUTOFF_T    45.0f

// ---- persistent scratch: built once per batch by K1, consumed by K2 ----
__device__ float4 g_pts[BATCH * N_IN];          // scaled (sx, sy, yval, pad), cell-sorted
__device__ int    g_start[BATCH * (NCELL + 1)]; // cell row starts (exclusive scan)

__device__ __forceinline__ float ex2_approx(float x) {
    float r;
    asm("ex2.approx.ftz.f32 %0, %1;" : "=f"(r) : "f"(x));
    return r;
}

__device__ __forceinline__ int cell_of(float v) {
    int c = (int)((v + 2.0f) * INV_CELL);
    return min(GRID - 1, max(0, c));
}

// ============================================================================
// K1: per-batch grid build. 8 blocks x 256 threads, 4 points/thread.
// ============================================================================
__global__ __launch_bounds__(256, 1)
void build_kernel(const float* __restrict__ x,
                  const float* __restrict__ y,
                  const float* __restrict__ sigma)
{
    __shared__ int cnt[NCELL];
    __shared__ int ofs[NCELL];
    __shared__ int wsum[8];
    __shared__ int woff[8];

    const int b    = blockIdx.x;
    const int tid  = threadIdx.x;
    const int lane = tid & 31;
    const int wid  = tid >> 5;             // 0..7

    // independent loads first
    const float2* __restrict__ xb = (const float2*)(x + (size_t)b * N_IN * 2);
    const float*  __restrict__ yb = y + (size_t)b * N_IN;
    float2 pxv[4]; float pyv[4]; int pcell[4];
    #pragma unroll
    for (int k = 0; k < 4; ++k) {
        int i = tid + k * 256;
        pxv[k] = xb[i];
        pyv[k] = yb[i];
    }

    const float LOG2E = 1.4426950408889634f;
    const float s0 = expf(sigma[0]);
    const float u0 = sqrtf(0.5f * LOG2E) / s0;   // coord scale

    if (tid < NCELL) cnt[tid] = 0;
    __syncthreads();

    #pragma unroll
    for (int k = 0; k < 4; ++k) {
        int c = cell_of(pxv[k].y) * GRID + cell_of(pxv[k].x);
        pcell[k] = c;
        atomicAdd(&cnt[c], 1);
    }
    __syncthreads();

    // ---- parallel exclusive scan: 6 warps scan 32 cells each ----
    int v = 0, excl_in_warp = 0;
    if (wid < 6) {
        int c = wid * 32 + lane;
        v = (c < NCELL) ? cnt[c] : 0;
        int s = v;
        #pragma unroll
        for (int off = 1; off < 32; off <<= 1) {
            int n = __shfl_up_sync(0xffffffffu, s, off);
            if (lane >= off) s += n;
        }
        excl_in_warp = s - v;
        if (lane == 31) wsum[wid] = s;
    }
    __syncthreads();
    if (tid == 0) {
        int acc = 0;
        #pragma unroll
        for (int w = 0; w < 6; ++w) { woff[w] = acc; acc += wsum[w]; }
        g_start[b * (NCELL + 1) + NCELL] = acc;   // == N_IN
    }
    __syncthreads();
    if (wid < 6) {
        int c = wid * 32 + lane;
        if (c < NCELL) {
            int e = excl_in_warp + woff[wid];
            ofs[c] = e;
            g_start[b * (NCELL + 1) + c] = e;
        }
    }
    __syncthreads();

    // ---- scatter scaled points to global ----
    float4* __restrict__ gp = g_pts + (size_t)b * N_IN;
    #pragma unroll
    for (int k = 0; k < 4; ++k) {
        int slot = atomicAdd(&ofs[pcell[k]], 1);
        gp[slot] = make_float4(pxv[k].x * u0, pxv[k].y * u0, pyv[k], 0.0f);
    }
}

// ============================================================================
// K2: query + epilogue. 128 blocks x 1024 threads.
// ============================================================================
__global__ __launch_bounds__(THREADS, 1)
void query_kernel(const float* __restrict__ t,
                  const float* __restrict__ sigma,
                  const float* __restrict__ W,
                  const float* __restrict__ bias,
                  float* __restrict__ out)
{
    __shared__ float4 pts[N_IN];
    __shared__ int    start[NCELL + 1];
    __shared__ float  dens_s[M_PER_BLOCK];
    __shared__ float  q_s[M_PER_BLOCK];
    __shared__ float  Ws[2 * OC];
    __shared__ float  bs[OC];

    const int b   = blockIdx.y;
    const int tid = threadIdx.x;

    // target mapping: ml = tid>>2, sub = tid&3 (4 consecutive lanes per target)
    const int ml  = tid >> 2;
    const int sub = tid & (NSUB - 1);
    const int m   = blockIdx.x * M_PER_BLOCK + ml;

    // ---- kick off all global loads first (MLP: three independent LDGs) ----
    const float2 tv = ((const float2*)(t + (size_t)b * N_OUT * 2))[m];
    const float4 pv = g_pts[(size_t)b * N_IN + tid];      // stage one point
    int sv = 0;
    if (tid < NCELL + 1) sv = g_start[b * (NCELL + 1) + tid];

    const float LOG2E = 1.4426950408889634f;
    const float s0 = expf(sigma[0]);
    const float s1 = expf(sigma[1]);
    const float u0    = sqrtf(0.5f * LOG2E) / s0;
    const float ratio = (s0 * s0) / (s1 * s1);
    const bool  equal_sig = (s0 == s1);

    const float smax = fmaxf(s0, s1);
    const float r_needed = sqrtf(2.0f * CUTOFF_T) * smax;
    int nb = (int)ceilf(r_needed * INV_CELL);
    nb = max(1, min(GRID - 1, nb));

    // ---- stage into smem ----
    pts[tid] = pv;
    if (tid < NCELL + 1) start[tid] = sv;
    if (tid < 2 * OC) Ws[tid] = W[tid];
    else if (tid >= 128 && tid < 128 + OC) bs[tid - 128] = bias[tid - 128];
    __syncthreads();

    // ---- query ----
    const float stx = tv.x * u0;
    const float sty = tv.y * u0;

    const int cx = cell_of(tv.x);
    const int cy = cell_of(tv.y);
    const int cx0 = max(0, cx - nb), cx1 = min(GRID - 1, cx + nb);
    const int cy0 = max(0, cy - nb), cy1 = min(GRID - 1, cy + nb);

    float acc0 = 0.0f;
    float acc1 = 0.0f;

    if (equal_sig) {
        for (int ry = cy0; ry <= cy1; ++ry) {
            int js = start[ry * GRID + cx0];
            int je = start[ry * GRID + cx1 + 1];
            #pragma unroll 2
            for (int j = js + sub; j < je; j += NSUB) {
                float4 p = pts[j];                 // group lanes: 64B contiguous
                float dx = p.x - stx;
                float dy = p.y - sty;
                float d  = fmaf(dy, dy, dx * dx);
                float e0 = ex2_approx(-d);
                acc0 += e0;
                acc1 = fmaf(p.z, e0, acc1);
            }
        }
    } else {
        for (int ry = cy0; ry <= cy1; ++ry) {
            int js = start[ry * GRID + cx0];
            int je = start[ry * GRID + cx1 + 1];
            #pragma unroll 2
            for (int j = js + sub; j < je; j += NSUB) {
                float4 p = pts[j];
                float dx = p.x - stx;
                float dy = p.y - sty;
                float d  = fmaf(dy, dy, dx * dx);
                float e0 = ex2_approx(-d);
                float e1 = ex2_approx(-d * ratio);
                acc0 += e0;
                acc1 = fmaf(p.z, e1, acc1);
            }
        }
    }

    // in-warp reduction over 4 sub-lanes
    acc0 += __shfl_xor_sync(0xffffffffu, acc0, 1, 4);
    acc1 += __shfl_xor_sync(0xffffffffu, acc1, 1, 4);
    acc0 += __shfl_xor_sync(0xffffffffu, acc0, 2, 4);
    acc1 += __shfl_xor_sync(0xffffffffu, acc1, 2, 4);

    if (sub == 0) {
        dens_s[ml] = acc0;
        q_s[ml]    = acc1 / (acc0 + 1e-8f);
    }
    __syncthreads();

    // ---- epilogue ----
    float4* __restrict__ ob =
        (float4*)(out + ((size_t)b * N_OUT + (size_t)blockIdx.x * M_PER_BLOCK) * OC);

    #pragma unroll
    for (int i = tid; i < M_PER_BLOCK * OC / 4; i += THREADS) {
        int m_local = i >> 4;
        int o0      = (i & 15) * 4;
        float f0 = dens_s[m_local];
        float f1 = q_s[m_local];
        float4 v;
        v.x = fmaf(f0, Ws[(o0 + 0) * 2], fmaf(f1, Ws[(o0 + 0) * 2 + 1], bs[o0 + 0]));
        v.y = fmaf(f0, Ws[(o0 + 1) * 2], fmaf(f1, Ws[(o0 + 1) * 2 + 1], bs[o0 + 1]));
        v.z = fmaf(f0, Ws[(o0 + 2) * 2], fmaf(f1, Ws[(o0 + 2) * 2 + 1], bs[o0 + 2]));
        v.w = fmaf(f0, Ws[(o0 + 3) * 2], fmaf(f1, Ws[(o0 + 3) * 2 + 1], bs[o0 + 3]));
        ob[i] = v;
    }
}

extern "C" void kernel_launch(void* const* d_in, const int* in_sizes, int n_in,
                              void* d_out, int out_size)
{
    const float* x     = (const float*)d_in[0];
    const float* y     = (const float*)d_in[1];
    const float* t     = (const float*)d_in[2];
    const float* sigma = (const float*)d_in[3];
    const float* W     = (const float*)d_in[4];
    const float* bias  = (const float*)d_in[5];
    float* out = (float*)d_out;

    build_kernel<<<BATCH, 256>>>(x, y, sigma);

    dim3 grid(N_OUT / M_PER_BLOCK, BATCH);   // 16 x 8 = 128 blocks
    query_kernel<<<grid, THREADS>>>(t, sigma, W, bias, out);
}